// round 1
// baseline (speedup 1.0000x reference)
#include <cuda_runtime.h>
#include <cuda_bf16.h>
#include <math.h>

// ---------------- problem constants ----------------
#define BB    8
#define SS    512
#define DD    2048
#define HH    16
#define DOWN  512
#define UP    2048
#define RR    512
#define VHD   128          // UP/H
#define MROWS (BB*SS)      // 4096
#define ZB    (BB*HH)      // 128 batched heads
#define QKDIM (VHD+RR)     // 640
#define INV_SCALE 0.0294627825494394758f   // 1/(sqrt(128)+sqrt(512))

// ---------------- scratch (device globals; no allocs allowed) ----------------
__device__ float g_cq  [(size_t)MROWS*DOWN];
__device__ float g_ckv [(size_t)MROWS*DOWN];
__device__ float g_qc  [(size_t)MROWS*UP];
__device__ float g_kc  [(size_t)MROWS*UP];
__device__ float g_vc  [(size_t)MROWS*UP];
__device__ float g_qr  [(size_t)MROWS*RR*HH];
__device__ float g_kr  [(size_t)MROWS*RR];
__device__ float g_krr [(size_t)MROWS*RR];
__device__ float g_qf  [(size_t)ZB*SS*QKDIM];
__device__ float g_kf  [(size_t)ZB*SS*QKDIM];
__device__ float g_sc  [(size_t)ZB*SS*SS];
__device__ float g_of  [(size_t)MROWS*UP];
__device__ float g_sin [SS*(RR/2)];
__device__ float g_cos [SS*(RR/2)];

// ---------------- generic 128x128x8 fp32 GEMM tile ----------------
// TB=false: C = A[M,K](lda) * B[K,N](ldb)    (row-major both)
// TB=true : C = A[M,K](lda) * B[N,K](ldb)^T
template<bool TB>
__device__ __forceinline__ void gemm_tile(
    const float* __restrict__ A, int lda,
    const float* __restrict__ B, int ldb,
    const float* __restrict__ bias, float scale,
    float* __restrict__ C, int ldc, int K,
    int brow, int bcol)
{
    __shared__ float As[8][128];
    __shared__ float Bs[8][128];
    const int tid = threadIdx.x;

    const float* Ab = A + (size_t)brow * 128 * lda;

    const int a_row  = tid >> 1;         // 0..127
    const int a_col  = (tid & 1) * 4;    // 0 or 4
    const int bn_row = tid >> 5;         // 0..7   (k)
    const int bn_col = (tid & 31) * 4;   // 0..124 (n)
    const int bt_row = tid >> 1;         // 0..127 (n)
    const int bt_col = (tid & 1) * 4;    // 0 or 4 (k)

    const int trow = (tid >> 4) * 8;
    const int tcol = (tid & 15) * 8;

    float acc[8][8];
    #pragma unroll
    for (int i = 0; i < 8; i++)
        #pragma unroll
        for (int j = 0; j < 8; j++) acc[i][j] = 0.f;

    for (int k0 = 0; k0 < K; k0 += 8) {
        float4 av = *(const float4*)(Ab + (size_t)a_row * lda + k0 + a_col);
        As[a_col+0][a_row] = av.x;
        As[a_col+1][a_row] = av.y;
        As[a_col+2][a_row] = av.z;
        As[a_col+3][a_row] = av.w;
        if (TB) {
            const float* Bb = B + (size_t)(bcol*128 + bt_row) * ldb;
            float4 bv = *(const float4*)(Bb + k0 + bt_col);
            Bs[bt_col+0][bt_row] = bv.x;
            Bs[bt_col+1][bt_row] = bv.y;
            Bs[bt_col+2][bt_row] = bv.z;
            Bs[bt_col+3][bt_row] = bv.w;
        } else {
            const float* Bb = B + (size_t)(k0 + bn_row) * ldb + bcol*128;
            *(float4*)&Bs[bn_row][bn_col] = *(const float4*)(Bb + bn_col);
        }
        __syncthreads();
        #pragma unroll
        for (int k = 0; k < 8; k++) {
            float rm[8], rn[8];
            *(float4*)(rm)   = *(const float4*)&As[k][trow];
            *(float4*)(rm+4) = *(const float4*)&As[k][trow+4];
            *(float4*)(rn)   = *(const float4*)&Bs[k][tcol];
            *(float4*)(rn+4) = *(const float4*)&Bs[k][tcol+4];
            #pragma unroll
            for (int i = 0; i < 8; i++)
                #pragma unroll
                for (int j = 0; j < 8; j++)
                    acc[i][j] = fmaf(rm[i], rn[j], acc[i][j]);
        }
        __syncthreads();
    }

    #pragma unroll
    for (int i = 0; i < 8; i++) {
        size_t row = (size_t)(brow*128 + trow + i);
        #pragma unroll
        for (int j = 0; j < 8; j += 4) {
            int col = bcol*128 + tcol + j;
            float4 o;
            o.x = acc[i][j+0] * scale;
            o.y = acc[i][j+1] * scale;
            o.z = acc[i][j+2] * scale;
            o.w = acc[i][j+3] * scale;
            if (bias) {
                o.x += bias[col+0]; o.y += bias[col+1];
                o.z += bias[col+2]; o.w += bias[col+3];
            }
            *(float4*)(C + row*ldc + col) = o;
        }
    }
}

// ---------------- projection GEMM wrappers (write to device globals) ----------
__global__ void __launch_bounds__(256) k_proj_cq(const float* X, const float* W, const float* b) {
    gemm_tile<false>(X, DD, W, DOWN, b, 1.f, g_cq, DOWN, DD, blockIdx.y, blockIdx.x);
}
__global__ void __launch_bounds__(256) k_proj_ckv(const float* X, const float* W, const float* b) {
    gemm_tile<false>(X, DD, W, DOWN, b, 1.f, g_ckv, DOWN, DD, blockIdx.y, blockIdx.x);
}
__global__ void __launch_bounds__(256) k_proj_kr(const float* X, const float* W, const float* b) {
    gemm_tile<false>(X, DD, W, RR, b, 1.f, g_kr, RR, DD, blockIdx.y, blockIdx.x);
}
__global__ void __launch_bounds__(256) k_proj_qc(const float* W, const float* b) {
    gemm_tile<false>(g_cq, DOWN, W, UP, b, 1.f, g_qc, UP, DOWN, blockIdx.y, blockIdx.x);
}
__global__ void __launch_bounds__(256) k_proj_qr(const float* W, const float* b) {
    gemm_tile<false>(g_cq, DOWN, W, RR*HH, b, 1.f, g_qr, RR*HH, DOWN, blockIdx.y, blockIdx.x);
}
__global__ void __launch_bounds__(256) k_proj_kc(const float* W, const float* b) {
    gemm_tile<false>(g_ckv, DOWN, W, UP, b, 1.f, g_kc, UP, DOWN, blockIdx.y, blockIdx.x);
}
__global__ void __launch_bounds__(256) k_proj_vc(const float* W, const float* b) {
    gemm_tile<false>(g_ckv, DOWN, W, UP, b, 1.f, g_vc, UP, DOWN, blockIdx.y, blockIdx.x);
}
__global__ void __launch_bounds__(256) k_final(const float* W, const float* b, float* out) {
    gemm_tile<false>(g_of, UP, W, DD, b, 1.f, out, DD, DD, blockIdx.y, blockIdx.x);
}

// ---------------- attention GEMMs -------------------------------------------
__global__ void __launch_bounds__(256) k_scores() {
    int z = blockIdx.z;
    gemm_tile<true>(g_qf + (size_t)z*SS*QKDIM, QKDIM,
                    g_kf + (size_t)z*SS*QKDIM, QKDIM,
                    nullptr, INV_SCALE,
                    g_sc + (size_t)z*SS*SS, SS, QKDIM,
                    blockIdx.y, blockIdx.x);
}
__global__ void __launch_bounds__(256) k_pv() {
    int z = blockIdx.y;
    int b = z >> 4, h = z & 15;
    gemm_tile<false>(g_sc + (size_t)z*SS*SS, SS,
                     g_vc + (size_t)b*SS*UP + h*VHD, UP,
                     nullptr, 1.f,
                     g_of + (size_t)b*SS*UP + h*VHD, UP, SS,
                     blockIdx.x, 0);
}

// ---------------- RoPE table + application ----------------------------------
__global__ void k_table() {
    int idx = blockIdx.x * 256 + threadIdx.x;   // 512*256
    int s = idx >> 8;
    int i = idx & 255;
    float div = expf((float)(2*i) * (-9.210340371976184f / (float)RR)); // ln(10000)
    float theta = (float)s * div;
    float sn, cs;
    sincosf(theta, &sn, &cs);
    g_sin[idx] = sn;
    g_cos[idx] = cs;
}

__global__ void k_rope_k() {
    int idx = blockIdx.x * 256 + threadIdx.x;   // MROWS * 256
    int i   = idx & 255;
    int row = idx >> 8;
    int s   = row & (SS-1);
    float2 v = *(const float2*)(g_kr + (size_t)row*RR + 2*i);
    float sn = g_sin[s*256 + i], cs = g_cos[s*256 + i];
    float2 o;
    o.x = v.x*cs - v.y*sn;
    o.y = v.y*cs + v.x*sn;
    *(float2*)(g_krr + (size_t)row*RR + 2*i) = o;
}

// pack q_full[z][s][640]: first 128 = q_c copy, last 512 = rope(q_r)
__global__ void k_pack_q() {
    int idx = blockIdx.x * 256 + threadIdx.x;   // ZB*SS*320 pairs
    int p = idx % 320;
    int s = (idx / 320) & (SS-1);
    int z = idx / (320*SS);
    int b = z >> 4, h = z & 15;
    size_t rowoff = (size_t)(b*SS + s);
    float* dst = g_qf + ((size_t)z*SS + s)*QKDIM;
    if (p < 64) {
        float2 v = *(const float2*)(g_qc + rowoff*UP + h*VHD + 2*p);
        *(float2*)(dst + 2*p) = v;
    } else {
        int i = p - 64;
        float2 v = *(const float2*)(g_qr + rowoff*(RR*HH) + h*RR + 2*i);
        float sn = g_sin[s*256 + i], cs = g_cos[s*256 + i];
        float2 o;
        o.x = v.x*cs - v.y*sn;
        o.y = v.y*cs + v.x*sn;
        *(float2*)(dst + VHD + 2*i) = o;
    }
}

__global__ void k_pack_k() {
    int idx = blockIdx.x * 256 + threadIdx.x;   // ZB*SS*320 pairs
    int p = idx % 320;
    int s = (idx / 320) & (SS-1);
    int z = idx / (320*SS);
    int b = z >> 4, h = z & 15;
    size_t rowoff = (size_t)(b*SS + s);
    float* dst = g_kf + ((size_t)z*SS + s)*QKDIM;
    if (p < 64) {
        float2 v = *(const float2*)(g_kc + rowoff*UP + h*VHD + 2*p);
        *(float2*)(dst + 2*p) = v;
    } else {
        int i = p - 64;
        float2 v = *(const float2*)(g_krr + rowoff*RR + 2*i);  // already roped, h-independent
        *(float2*)(dst + VHD + 2*i) = v;
    }
}

// ---------------- softmax over last axis (512) --------------------------------
__global__ void __launch_bounds__(128) k_softmax() {
    size_t row = blockIdx.x;                    // ZB*SS*... = 128*512 rows... wait: ZB*SS = 65536 rows
    float* p = g_sc + row * SS;
    int t = threadIdx.x;                        // 128 threads, 4 floats each
    float4 v = ((float4*)p)[t];
    float m = fmaxf(fmaxf(v.x, v.y), fmaxf(v.z, v.w));
    #pragma unroll
    for (int o = 16; o; o >>= 1) m = fmaxf(m, __shfl_xor_sync(0xffffffffu, m, o));
    __shared__ float redm[4], reds[4];
    if ((t & 31) == 0) redm[t >> 5] = m;
    __syncthreads();
    m = fmaxf(fmaxf(redm[0], redm[1]), fmaxf(redm[2], redm[3]));
    v.x = __expf(v.x - m); v.y = __expf(v.y - m);
    v.z = __expf(v.z - m); v.w = __expf(v.w - m);
    float s = v.x + v.y + v.z + v.w;
    #pragma unroll
    for (int o = 16; o; o >>= 1) s += __shfl_xor_sync(0xffffffffu, s, o);
    if ((t & 31) == 0) reds[t >> 5] = s;
    __syncthreads();
    s = reds[0] + reds[1] + reds[2] + reds[3];
    float inv = 1.f / s;
    v.x *= inv; v.y *= inv; v.z *= inv; v.w *= inv;
    ((float4*)p)[t] = v;
}

// ---------------- launch ------------------------------------------------------
extern "C" void kernel_launch(void* const* d_in, const int* in_sizes, int n_in,
                              void* d_out, int out_size)
{
    const float* X    = (const float*)d_in[0];
    const float* Wdq  = (const float*)d_in[1];
    const float* bdq  = (const float*)d_in[2];
    const float* Wdkv = (const float*)d_in[3];
    const float* bdkv = (const float*)d_in[4];
    const float* Wuq  = (const float*)d_in[5];
    const float* buq  = (const float*)d_in[6];
    const float* Wuk  = (const float*)d_in[7];
    const float* buk  = (const float*)d_in[8];
    const float* Wuv  = (const float*)d_in[9];
    const float* buv  = (const float*)d_in[10];
    const float* Wqr  = (const float*)d_in[11];
    const float* bqr  = (const float*)d_in[12];
    const float* Wkr  = (const float*)d_in[13];
    const float* bkr  = (const float*)d_in[14];
    const float* Wfc  = (const float*)d_in[15];
    const float* bfc  = (const float*)d_in[16];
    float* out = (float*)d_out;

    // RoPE sin/cos tables: 512 pos x 256 pairs
    k_table<<<(SS*(RR/2))/256, 256>>>();

    // down-projections + rope-k projection (all from X, K=2048)
    k_proj_cq <<<dim3(DOWN/128,  MROWS/128), 256>>>(X, Wdq,  bdq);
    k_proj_ckv<<<dim3(DOWN/128,  MROWS/128), 256>>>(X, Wdkv, bdkv);
    k_proj_kr <<<dim3(RR/128,    MROWS/128), 256>>>(X, Wkr,  bkr);

    // up-projections (K=512)
    k_proj_qc<<<dim3(UP/128,      MROWS/128), 256>>>(Wuq, buq);
    k_proj_qr<<<dim3((RR*HH)/128, MROWS/128), 256>>>(Wqr, bqr);
    k_proj_kc<<<dim3(UP/128,      MROWS/128), 256>>>(Wuk, buk);
    k_proj_vc<<<dim3(UP/128,      MROWS/128), 256>>>(Wuv, buv);

    // rope k_r once (shared across heads), then pack Q/K into [z][s][640]
    k_rope_k<<<(MROWS*(RR/2))/256, 256>>>();
    k_pack_q<<<(ZB*SS*320)/256, 256>>>();
    k_pack_k<<<(ZB*SS*320)/256, 256>>>();

    // attention: scores (QK^T / scale), softmax, PV (scatter into [b,s,h*128+d])
    k_scores <<<dim3(SS/128, SS/128, ZB), 256>>>();
    k_softmax<<<ZB*SS, 128>>>();
    k_pv     <<<dim3(SS/128, ZB), 256>>>();

    // output projection -> d_out
    k_final<<<dim3(DD/128, MROWS/128), 256>>>(Wfc, bfc, out);
}